// round 2
// baseline (speedup 1.0000x reference)
#include <cuda_runtime.h>
#include <math.h>

// Problem constants (fixed by the reference: B=8, T=1024, C=768, H=8, D=96)
#define B_    8
#define T_    1024
#define C_    768
#define H_    8
#define DH    96
#define QKV3  2304   // 3*C

// Scratch (allocation-free rule: __device__ globals)
__device__ float g_qkv[(size_t)B_ * T_ * QKV3];   // 75.5 MB: qkv projection output
__device__ float g_att[(size_t)B_ * T_ * C_];     // 25.2 MB: attention output (B,T,C)

// ---------------------------------------------------------------------------
// GEMM: C[M,N] = A[M,K] @ B[N,K]^T + bias[N]
// Both A and B are K-major (row-major, K contiguous) -> dot along rows.
// 128x128 tile, BK=16, 256 threads, 8x8 per thread, split-register layout
// (rows {ty*4..+3, 64+ty*4..+3} x cols {tx*4..+3, 64+tx*4..+3}) so all
// LDS.128 reads are conflict-free / broadcast.
// DOUBLE-BUFFERED smem: one __syncthreads per K-tile; global prefetch of
// tile i+1 overlaps the 1024 FFMAs of tile i.
// Requires M%128==0, N%128==0, K%16==0 (true for all three shapes here).
// ---------------------------------------------------------------------------
__global__ __launch_bounds__(256) void sgemm_bias(
    const float* __restrict__ A, const float* __restrict__ Bw,
    const float* __restrict__ bias, float* __restrict__ C,
    int M, int N, int K)
{
    __shared__ float As[2][16][128];   // 16 KB
    __shared__ float Bs[2][16][128];   // 16 KB

    const int tid = threadIdx.x;
    const int tx = tid & 15;       // 0..15 -> N
    const int ty = tid >> 4;       // 0..15 -> M
    const int bm = blockIdx.y * 128;
    const int bn = blockIdx.x * 128;

    // Load mapping: each thread loads 8 consecutive k (two float4) of one row
    const int lrow = tid >> 1;           // 0..127
    const int lk   = (tid & 1) * 8;      // 0 or 8
    const float* Ap = A  + (size_t)(bm + lrow) * K + lk;
    const float* Bp = Bw + (size_t)(bn + lrow) * K + lk;

    float acc[8][8];
#pragma unroll
    for (int i = 0; i < 8; i++)
#pragma unroll
        for (int j = 0; j < 8; j++) acc[i][j] = 0.f;

    const int nt = K / 16;               // number of K-tiles

    // Preload tile 0
    float4 a0 = *(const float4*)(Ap);
    float4 a1 = *(const float4*)(Ap + 4);
    float4 b0 = *(const float4*)(Bp);
    float4 b1 = *(const float4*)(Bp + 4);
    {
        float (*as)[128] = As[0];
        float (*bs)[128] = Bs[0];
        as[lk + 0][lrow] = a0.x;  as[lk + 1][lrow] = a0.y;
        as[lk + 2][lrow] = a0.z;  as[lk + 3][lrow] = a0.w;
        as[lk + 4][lrow] = a1.x;  as[lk + 5][lrow] = a1.y;
        as[lk + 6][lrow] = a1.z;  as[lk + 7][lrow] = a1.w;
        bs[lk + 0][lrow] = b0.x;  bs[lk + 1][lrow] = b0.y;
        bs[lk + 2][lrow] = b0.z;  bs[lk + 3][lrow] = b0.w;
        bs[lk + 4][lrow] = b1.x;  bs[lk + 5][lrow] = b1.y;
        bs[lk + 6][lrow] = b1.z;  bs[lk + 7][lrow] = b1.w;
    }
    __syncthreads();

    for (int it = 0; it < nt; it++) {
        const int cur = it & 1;

        // Prefetch next tile into registers (overlaps with compute below)
        if (it + 1 < nt) {
            const int k0 = (it + 1) * 16;
            a0 = *(const float4*)(Ap + k0);
            a1 = *(const float4*)(Ap + k0 + 4);
            b0 = *(const float4*)(Bp + k0);
            b1 = *(const float4*)(Bp + k0 + 4);
        }

        // Compute on current buffer
        {
            float (*as)[128] = As[cur];
            float (*bs)[128] = Bs[cur];
#pragma unroll
            for (int kk = 0; kk < 16; kk++) {
                float a[8], b[8];
                *(float4*)(a)     = *(const float4*)&as[kk][ty * 4];
                *(float4*)(a + 4) = *(const float4*)&as[kk][64 + ty * 4];
                *(float4*)(b)     = *(const float4*)&bs[kk][tx * 4];
                *(float4*)(b + 4) = *(const float4*)&bs[kk][64 + tx * 4];
#pragma unroll
                for (int i = 0; i < 8; i++)
#pragma unroll
                    for (int j = 0; j < 8; j++) acc[i][j] += a[i] * b[j];
            }
        }

        // Store prefetched tile into the other buffer; single sync per iter.
        // Safe: buf cur^1 was last READ in iteration it-1, which all threads
        // left at the barrier ending that iteration.
        if (it + 1 < nt) {
            float (*as)[128] = As[cur ^ 1];
            float (*bs)[128] = Bs[cur ^ 1];
            as[lk + 0][lrow] = a0.x;  as[lk + 1][lrow] = a0.y;
            as[lk + 2][lrow] = a0.z;  as[lk + 3][lrow] = a0.w;
            as[lk + 4][lrow] = a1.x;  as[lk + 5][lrow] = a1.y;
            as[lk + 6][lrow] = a1.z;  as[lk + 7][lrow] = a1.w;
            bs[lk + 0][lrow] = b0.x;  bs[lk + 1][lrow] = b0.y;
            bs[lk + 2][lrow] = b0.z;  bs[lk + 3][lrow] = b0.w;
            bs[lk + 4][lrow] = b1.x;  bs[lk + 5][lrow] = b1.y;
            bs[lk + 6][lrow] = b1.z;  bs[lk + 7][lrow] = b1.w;
            __syncthreads();
        }
    }

    // Epilogue: bias + store (two float4 per output row)
    const int c0 = bn + tx * 4;
    const int c1 = bn + 64 + tx * 4;
    const float4 bv0 = *(const float4*)&bias[c0];
    const float4 bv1 = *(const float4*)&bias[c1];
#pragma unroll
    for (int i = 0; i < 8; i++) {
        const int r = bm + ((i < 4) ? (ty * 4 + i) : (64 + ty * 4 + i - 4));
        float4 o0, o1;
        o0.x = acc[i][0] + bv0.x; o0.y = acc[i][1] + bv0.y;
        o0.z = acc[i][2] + bv0.z; o0.w = acc[i][3] + bv0.w;
        o1.x = acc[i][4] + bv1.x; o1.y = acc[i][5] + bv1.y;
        o1.z = acc[i][6] + bv1.z; o1.w = acc[i][7] + bv1.w;
        *(float4*)&C[(size_t)r * N + c0] = o0;
        *(float4*)&C[(size_t)r * N + c1] = o1;
    }
}

// ---------------------------------------------------------------------------
// Flash-style causal attention, fp32.
// Grid: (T/64, H, B). Block: 256 threads.
// 64 queries per block; each query owned by 4 consecutive lanes (dg=0..3),
// each lane accumulates 24 of the 96 head dims. K/V streamed in 32-row tiles
// through shared memory. Online softmax (m, l) per query, shared across the
// 4 lanes via shfl. Reads q,k,v straight out of the fused qkv buffer.
// ---------------------------------------------------------------------------
__global__ __launch_bounds__(256) void attn_kernel(
    const float* __restrict__ qkv, float* __restrict__ out)
{
    __shared__ float Ks[32][96];   // 12 KB
    __shared__ float Vs[32][96];   // 12 KB
    __shared__ float S[64][33];    // 8.25 KB, padded stride -> conflict-free

    const int qt = blockIdx.x;
    const int h  = blockIdx.y;
    const int b  = blockIdx.z;
    const int tid = threadIdx.x;
    const int ql = tid >> 2;       // 0..63 query within tile
    const int dg = tid & 3;        // dim group: dims [dg*24, dg*24+24)
    const int qglob = qt * 64 + ql;

    const float scale = rsqrtf((float)DH);

    // Load this thread's 24 query dims (pre-scaled)
    float qreg[24];
    {
        const float* qb = qkv + (size_t)(b * T_ + qglob) * QKV3 + h * DH + dg * 24;
#pragma unroll
        for (int i4 = 0; i4 < 6; i4++) {
            float4 v = *(const float4*)(qb + i4 * 4);
            qreg[i4 * 4 + 0] = v.x * scale;
            qreg[i4 * 4 + 1] = v.y * scale;
            qreg[i4 * 4 + 2] = v.z * scale;
            qreg[i4 * 4 + 3] = v.w * scale;
        }
    }

    float acc[24];
#pragma unroll
    for (int i = 0; i < 24; i++) acc[i] = 0.f;
    float m = -INFINITY, l = 0.f;

    const int ktmax = qt * 2 + 1;   // last K-tile touching the causal region
    for (int kt = 0; kt <= ktmax; kt++) {
        // Cooperative load of K and V tiles (32 rows x 96 dims, float4s)
        for (int idx = tid; idx < 768; idx += 256) {
            const int row = idx / 24;
            const int c4  = (idx % 24) * 4;
            const size_t gb = (size_t)(b * T_ + kt * 32 + row) * QKV3 + h * DH + c4;
            *(float4*)&Ks[row][c4] = *(const float4*)(qkv + gb + C_);
            *(float4*)&Vs[row][c4] = *(const float4*)(qkv + gb + 2 * C_);
        }
        __syncthreads();

        // Scores: each (ql,dg) group computes all 32 scores cooperatively
        const int kbase = kt * 32;
#pragma unroll 4
        for (int k = 0; k < 32; k++) {
            const float* kp = &Ks[k][dg * 24];
            float s = 0.f;
#pragma unroll
            for (int i = 0; i < 24; i++) s += qreg[i] * kp[i];
            s += __shfl_xor_sync(0xffffffffu, s, 1);
            s += __shfl_xor_sync(0xffffffffu, s, 2);
            if (kbase + k > qglob) s = -INFINITY;   // causal mask
            if (dg == 0) S[ql][k] = s;
        }
        __syncwarp();

        // Tile max -> online softmax update
        float tm = -INFINITY;
#pragma unroll
        for (int j = 0; j < 8; j++) tm = fmaxf(tm, S[ql][dg * 8 + j]);
        tm = fmaxf(tm, __shfl_xor_sync(0xffffffffu, tm, 1));
        tm = fmaxf(tm, __shfl_xor_sync(0xffffffffu, tm, 2));
        const float newm = fmaxf(m, tm);          // finite after first tile
        const float corr = __expf(m - newm);      // __expf(-inf)=0 on first tile
        l *= corr;
#pragma unroll
        for (int i = 0; i < 24; i++) acc[i] *= corr;

        float psum = 0.f;
#pragma unroll
        for (int j = 0; j < 8; j++) {
            const int k = dg * 8 + j;
            const float p = __expf(S[ql][k] - newm);  // masked -> exp(-inf)=0
            S[ql][k] = p;
            psum += p;
        }
        psum += __shfl_xor_sync(0xffffffffu, psum, 1);
        psum += __shfl_xor_sync(0xffffffffu, psum, 2);
        l += psum;
        m = newm;
        __syncwarp();

        // P @ V
#pragma unroll 4
        for (int k = 0; k < 32; k++) {
            const float p = S[ql][k];
            const float* vp = &Vs[k][dg * 24];
#pragma unroll
            for (int i = 0; i < 24; i++) acc[i] += p * vp[i];
        }
        __syncthreads();   // before next tile overwrites Ks/Vs
    }

    // Epilogue: normalize and store to (B,T,C) layout
    const float inv = 1.f / l;
    float* ob = out + (size_t)(b * T_ + qglob) * C_ + h * DH + dg * 24;
#pragma unroll
    for (int i4 = 0; i4 < 6; i4++) {
        float4 v;
        v.x = acc[i4 * 4 + 0] * inv;
        v.y = acc[i4 * 4 + 1] * inv;
        v.z = acc[i4 * 4 + 2] * inv;
        v.w = acc[i4 * 4 + 3] * inv;
        *(float4*)(ob + i4 * 4) = v;
    }
}

// ---------------------------------------------------------------------------
// Launch: QKV GEMM -> attention -> projection GEMM
// Inputs (metadata order): x, c_attn_weight, c_attn_bias, c_proj_weight,
//                          c_proj_bias, bias(causal mask, unused)
// ---------------------------------------------------------------------------
extern "C" void kernel_launch(void* const* d_in, const int* in_sizes, int n_in,
                              void* d_out, int out_size)
{
    const float* x     = (const float*)d_in[0];
    const float* Wqkv  = (const float*)d_in[1];
    const float* bqkv  = (const float*)d_in[2];
    const float* Wproj = (const float*)d_in[3];
    const float* bproj = (const float*)d_in[4];
    float* out = (float*)d_out;

    float *qkv, *att;
    cudaGetSymbolAddress((void**)&qkv, g_qkv);
    cudaGetSymbolAddress((void**)&att, g_att);

    const int M = B_ * T_;   // 8192

    // qkv = x @ Wqkv^T + bqkv   (8192 x 2304 x 768)
    sgemm_bias<<<dim3(QKV3 / 128, M / 128), 256>>>(x, Wqkv, bqkv, qkv, M, QKV3, C_);

    // attention (flash-style, causal)
    attn_kernel<<<dim3(T_ / 64, H_, B_), 256>>>(qkv, att);

    // y = att @ Wproj^T + bproj  (8192 x 768 x 768)
    sgemm_bias<<<dim3(C_ / 128, M / 128), 256>>>(att, Wproj, bproj, out, M, C_, C_);
}

// round 4
// speedup vs baseline: 1.5577x; 1.5577x over previous
#include <cuda_runtime.h>
#include <math.h>

// Problem constants (fixed by the reference: B=8, T=1024, C=768, H=8, D=96)
#define B_    8
#define T_    1024
#define C_    768
#define H_    8
#define DH    96
#define QKV3  2304   // 3*C

// Scratch (allocation-free rule: __device__ globals)
__device__ float g_qkv[(size_t)B_ * T_ * QKV3];   // 75.5 MB: qkv projection output
__device__ float g_att[(size_t)B_ * T_ * C_];     // 25.2 MB: attention output (B,T,C)

// ---------------------------------------------------------------------------
// GEMM: C[M,N] = A[M,K] @ B[N,K]^T + bias[N]   (measured: 66% fma, 78% issue)
// 128x128 tile, BK=16, 256 threads, 8x8/thread, double-buffered smem.
// ---------------------------------------------------------------------------
__global__ __launch_bounds__(256) void sgemm_bias(
    const float* __restrict__ A, const float* __restrict__ Bw,
    const float* __restrict__ bias, float* __restrict__ C,
    int M, int N, int K)
{
    __shared__ float As[2][16][128];
    __shared__ float Bs[2][16][128];

    const int tid = threadIdx.x;
    const int tx = tid & 15;
    const int ty = tid >> 4;
    const int bm = blockIdx.y * 128;
    const int bn = blockIdx.x * 128;

    const int lrow = tid >> 1;
    const int lk   = (tid & 1) * 8;
    const float* Ap = A  + (size_t)(bm + lrow) * K + lk;
    const float* Bp = Bw + (size_t)(bn + lrow) * K + lk;

    float acc[8][8];
#pragma unroll
    for (int i = 0; i < 8; i++)
#pragma unroll
        for (int j = 0; j < 8; j++) acc[i][j] = 0.f;

    const int nt = K / 16;

    float4 a0 = *(const float4*)(Ap);
    float4 a1 = *(const float4*)(Ap + 4);
    float4 b0 = *(const float4*)(Bp);
    float4 b1 = *(const float4*)(Bp + 4);
    {
        float (*as)[128] = As[0];
        float (*bs)[128] = Bs[0];
        as[lk + 0][lrow] = a0.x;  as[lk + 1][lrow] = a0.y;
        as[lk + 2][lrow] = a0.z;  as[lk + 3][lrow] = a0.w;
        as[lk + 4][lrow] = a1.x;  as[lk + 5][lrow] = a1.y;
        as[lk + 6][lrow] = a1.z;  as[lk + 7][lrow] = a1.w;
        bs[lk + 0][lrow] = b0.x;  bs[lk + 1][lrow] = b0.y;
        bs[lk + 2][lrow] = b0.z;  bs[lk + 3][lrow] = b0.w;
        bs[lk + 4][lrow] = b1.x;  bs[lk + 5][lrow] = b1.y;
        bs[lk + 6][lrow] = b1.z;  bs[lk + 7][lrow] = b1.w;
    }
    __syncthreads();

    for (int it = 0; it < nt; it++) {
        const int cur = it & 1;

        if (it + 1 < nt) {
            const int k0 = (it + 1) * 16;
            a0 = *(const float4*)(Ap + k0);
            a1 = *(const float4*)(Ap + k0 + 4);
            b0 = *(const float4*)(Bp + k0);
            b1 = *(const float4*)(Bp + k0 + 4);
        }

        {
            float (*as)[128] = As[cur];
            float (*bs)[128] = Bs[cur];
#pragma unroll
            for (int kk = 0; kk < 16; kk++) {
                float a[8], b[8];
                *(float4*)(a)     = *(const float4*)&as[kk][ty * 4];
                *(float4*)(a + 4) = *(const float4*)&as[kk][64 + ty * 4];
                *(float4*)(b)     = *(const float4*)&bs[kk][tx * 4];
                *(float4*)(b + 4) = *(const float4*)&bs[kk][64 + tx * 4];
#pragma unroll
                for (int i = 0; i < 8; i++)
#pragma unroll
                    for (int j = 0; j < 8; j++) acc[i][j] += a[i] * b[j];
            }
        }

        if (it + 1 < nt) {
            float (*as)[128] = As[cur ^ 1];
            float (*bs)[128] = Bs[cur ^ 1];
            as[lk + 0][lrow] = a0.x;  as[lk + 1][lrow] = a0.y;
            as[lk + 2][lrow] = a0.z;  as[lk + 3][lrow] = a0.w;
            as[lk + 4][lrow] = a1.x;  as[lk + 5][lrow] = a1.y;
            as[lk + 6][lrow] = a1.z;  as[lk + 7][lrow] = a1.w;
            bs[lk + 0][lrow] = b0.x;  bs[lk + 1][lrow] = b0.y;
            bs[lk + 2][lrow] = b0.z;  bs[lk + 3][lrow] = b0.w;
            bs[lk + 4][lrow] = b1.x;  bs[lk + 5][lrow] = b1.y;
            bs[lk + 6][lrow] = b1.z;  bs[lk + 7][lrow] = b1.w;
            __syncthreads();
        }
    }

    const int c0 = bn + tx * 4;
    const int c1 = bn + 64 + tx * 4;
    const float4 bv0 = *(const float4*)&bias[c0];
    const float4 bv1 = *(const float4*)&bias[c1];
#pragma unroll
    for (int i = 0; i < 8; i++) {
        const int r = bm + ((i < 4) ? (ty * 4 + i) : (64 + ty * 4 + i - 4));
        float4 o0, o1;
        o0.x = acc[i][0] + bv0.x; o0.y = acc[i][1] + bv0.y;
        o0.z = acc[i][2] + bv0.z; o0.w = acc[i][3] + bv0.w;
        o1.x = acc[i][4] + bv1.x; o1.y = acc[i][5] + bv1.y;
        o1.z = acc[i][6] + bv1.z; o1.w = acc[i][7] + bv1.w;
        *(float4*)&C[(size_t)r * N + c0] = o0;
        *(float4*)&C[(size_t)r * N + c1] = o1;
    }
}

// ---------------------------------------------------------------------------
// Register-tiled flash attention (causal), fp32.
// Grid: (16, H, B), block 256 threads, 2 blocks/SM.
// 64 queries x 64-key tiles. Thread (ty,tx), ty,tx in 0..15:
//   S-GEMM: 4x4 outer-product block -> 16 independent FFMA chains.
//   PV-GEMM: 4 q-rows x 6 dims per thread.
// Ks stored with XOR swizzle (c ^ ((k>>2)&7)): conflict-free LDS.128 on both
// the transposed-pattern reads and the coalesced writes.
// Qs padded to 100 floats/row; Ps padded to 68 floats/row.
// Dynamic smem: 92160 B (> 48KB static limit).
// ---------------------------------------------------------------------------
#define ATTN_SMEM ((64 * 100 + 64 * 96 + 64 * 96 + 64 * 68) * 4)

__global__ __launch_bounds__(256, 2) void attn_kernel(
    const float* __restrict__ qkv, float* __restrict__ out)
{
    extern __shared__ float sm[];
    float* Qs = sm;                    // [64][100]
    float* Ks = Qs + 64 * 100;         // [64][96], swizzled
    float* Vs = Ks + 64 * 96;          // [64][96]
    float* Ps = Vs + 64 * 96;          // [64][68]

    const int qt = (int)gridDim.x - 1 - (int)blockIdx.x;  // heavy blocks first
    const int h  = blockIdx.y;
    const int b  = blockIdx.z;
    const int tid = threadIdx.x;
    const int tx = tid & 15;
    const int ty = tid >> 4;

    const float scale = rsqrtf((float)DH);

    // Load + pre-scale Q tile (64 x 96), coalesced
#pragma unroll
    for (int i = 0; i < 6; i++) {
        const int idx = tid + i * 256;
        const int q = idx / 24, c = idx % 24;
        const float* g = qkv + (size_t)(b * T_ + qt * 64 + q) * QKV3 + h * DH + c * 4;
        float4 v = *(const float4*)g;
        v.x *= scale; v.y *= scale; v.z *= scale; v.w *= scale;
        *(float4*)&Qs[q * 100 + c * 4] = v;
    }

    float o[4][6];
#pragma unroll
    for (int i = 0; i < 4; i++)
#pragma unroll
        for (int d = 0; d < 6; d++) o[i][d] = 0.f;
    float m[4], l[4];
#pragma unroll
    for (int i = 0; i < 4; i++) { m[i] = -INFINITY; l[i] = 0.f; }

    const int q0 = qt * 64 + ty * 4;   // first owned query (global index)
    const int ksw = tx & 7;            // read-side swizzle key

    for (int kt = 0; kt <= qt; kt++) {
        __syncthreads();   // Q tile ready (kt=0) / previous PV reads done
        const int kbase = kt * 64;

        // Load K (swizzled) and V tiles, coalesced float4
#pragma unroll
        for (int i = 0; i < 6; i++) {
            const int idx = tid + i * 256;
            const int k = idx / 24, c = idx % 24;
            const float* g = qkv + (size_t)(b * T_ + kbase + k) * QKV3 + C_ + h * DH + c * 4;
            const float4 kv = *(const float4*)g;
            const float4 vv = *(const float4*)(g + C_);
            *(float4*)&Ks[k * 96 + ((c ^ ((k >> 2) & 7)) << 2)] = kv;
            *(float4*)&Vs[k * 96 + c * 4] = vv;
        }
        __syncthreads();

        // ---- S = Q @ K^T (4x4 block per thread, outer product over dims) ----
        float s[4][4];
#pragma unroll
        for (int i = 0; i < 4; i++)
#pragma unroll
            for (int j = 0; j < 4; j++) s[i][j] = 0.f;

#pragma unroll
        for (int c = 0; c < 24; c++) {
            float4 qv[4], kv[4];
#pragma unroll
            for (int i = 0; i < 4; i++)
                qv[i] = *(const float4*)&Qs[(ty * 4 + i) * 100 + c * 4];
#pragma unroll
            for (int j = 0; j < 4; j++)
                kv[j] = *(const float4*)&Ks[(tx * 4 + j) * 96 + ((c ^ ksw) << 2)];
#pragma unroll
            for (int i = 0; i < 4; i++)
#pragma unroll
                for (int j = 0; j < 4; j++) {
                    s[i][j] += qv[i].x * kv[j].x;
                    s[i][j] += qv[i].y * kv[j].y;
                    s[i][j] += qv[i].z * kv[j].z;
                    s[i][j] += qv[i].w * kv[j].w;
                }
        }

        // ---- causal mask (only diagonal tile masks) + online softmax ----
        const bool diag = (kt == qt);
#pragma unroll
        for (int i = 0; i < 4; i++) {
            const int qg = q0 + i;
            if (diag) {
#pragma unroll
                for (int j = 0; j < 4; j++)
                    if (kbase + tx * 4 + j > qg) s[i][j] = -INFINITY;
            }
            float mx = fmaxf(fmaxf(s[i][0], s[i][1]), fmaxf(s[i][2], s[i][3]));
            mx = fmaxf(mx, __shfl_xor_sync(0xffffffffu, mx, 1));
            mx = fmaxf(mx, __shfl_xor_sync(0xffffffffu, mx, 2));
            mx = fmaxf(mx, __shfl_xor_sync(0xffffffffu, mx, 4));
            mx = fmaxf(mx, __shfl_xor_sync(0xffffffffu, mx, 8));
            const float mn = fmaxf(m[i], mx);
            const float corr = __expf(m[i] - mn);   // exp(-inf)=0 on first tile
            m[i] = mn;
            l[i] *= corr;
#pragma unroll
            for (int d = 0; d < 6; d++) o[i][d] *= corr;
            float p0 = __expf(s[i][0] - mn);
            float p1 = __expf(s[i][1] - mn);
            float p2 = __expf(s[i][2] - mn);
            float p3 = __expf(s[i][3] - mn);
            float ps = (p0 + p1) + (p2 + p3);
            ps += __shfl_xor_sync(0xffffffffu, ps, 1);
            ps += __shfl_xor_sync(0xffffffffu, ps, 2);
            ps += __shfl_xor_sync(0xffffffffu, ps, 4);
            ps += __shfl_xor_sync(0xffffffffu, ps, 8);
            l[i] += ps;
            *(float4*)&Ps[(ty * 4 + i) * 68 + tx * 4] = make_float4(p0, p1, p2, p3);
        }
        __syncthreads();

        // ---- O += P @ V  (4 q-rows x 6 dims per thread) ----
#pragma unroll 4
        for (int kk = 0; kk < 64; kk += 4) {
            float p[4][4];
#pragma unroll
            for (int i = 0; i < 4; i++) {
                const float4 pv = *(const float4*)&Ps[(ty * 4 + i) * 68 + kk];
                p[i][0] = pv.x; p[i][1] = pv.y; p[i][2] = pv.z; p[i][3] = pv.w;
            }
#pragma unroll
            for (int t = 0; t < 4; t++) {
                const float* vr = &Vs[(kk + t) * 96 + tx * 6];
                const float2 v0 = *(const float2*)(vr);
                const float2 v1 = *(const float2*)(vr + 2);
                const float2 v2 = *(const float2*)(vr + 4);
#pragma unroll
                for (int i = 0; i < 4; i++) {
                    const float pi = p[i][t];
                    o[i][0] += pi * v0.x; o[i][1] += pi * v0.y;
                    o[i][2] += pi * v1.x; o[i][3] += pi * v1.y;
                    o[i][4] += pi * v2.x; o[i][5] += pi * v2.y;
                }
            }
        }
    }

    // Epilogue: normalize and store (B,T,C)
#pragma unroll
    for (int i = 0; i < 4; i++) {
        const float inv = 1.f / l[i];
        float* ob = out + (size_t)(b * T_ + q0 + i) * C_ + h * DH + tx * 6;
        float2 w0, w1, w2;
        w0.x = o[i][0] * inv; w0.y = o[i][1] * inv;
        w1.x = o[i][2] * inv; w1.y = o[i][3] * inv;
        w2.x = o[i][4] * inv; w2.y = o[i][5] * inv;
        *(float2*)(ob)     = w0;
        *(float2*)(ob + 2) = w1;
        *(float2*)(ob + 4) = w2;
    }
}

// ---------------------------------------------------------------------------
// Launch: QKV GEMM -> attention -> projection GEMM
// ---------------------------------------------------------------------------
extern "C" void kernel_launch(void* const* d_in, const int* in_sizes, int n_in,
                              void* d_out, int out_size)
{
    const float* x     = (const float*)d_in[0];
    const float* Wqkv  = (const float*)d_in[1];
    const float* bqkv  = (const float*)d_in[2];
    const float* Wproj = (const float*)d_in[3];
    const float* bproj = (const float*)d_in[4];
    float* out = (float*)d_out;

    float *qkv, *att;
    cudaGetSymbolAddress((void**)&qkv, g_qkv);
    cudaGetSymbolAddress((void**)&att, g_att);

    const int M = B_ * T_;   // 8192

    // qkv = x @ Wqkv^T + bqkv   (8192 x 2304 x 768)
    sgemm_bias<<<dim3(QKV3 / 128, M / 128), 256>>>(x, Wqkv, bqkv, qkv, M, QKV3, C_);

    // attention (register-tiled flash, causal); needs >48KB smem -> dynamic
    cudaFuncSetAttribute(attn_kernel, cudaFuncAttributeMaxDynamicSharedMemorySize, ATTN_SMEM);
    attn_kernel<<<dim3(T_ / 64, H_, B_), 256, ATTN_SMEM>>>(qkv, att);

    // y = att @ Wproj^T + bproj  (8192 x 768 x 768)
    sgemm_bias<<<dim3(C_ / 128, M / 128), 256>>>(att, Wproj, bproj, out, M, C_, C_);
}